// round 1
// baseline (speedup 1.0000x reference)
#include <cuda_runtime.h>

#define NB 16
#define NM 32
#define NLH 128
#define NSTEPS 15
#define NPIX (NB*NM*NM)

// Scratch (static __device__ — allocation guards forbid cudaMalloc)
__device__ float g_hid[NPIX*NLH];
__device__ float g_hbuf[2][NPIX*NLH];
__device__ float g_cbuf[2][NPIX*NLH];

__device__ __forceinline__ float sigf(float x) {
    return __fdividef(1.0f, 1.0f + __expf(-x));
}
__device__ __forceinline__ float tanhx(float x) {
    return __fdividef(2.0f, 1.0f + __expf(-2.0f * x)) - 1.0f;
}

// ---------------------------------------------------------------------------
// Kernel 1: hid = conv3x3(X, W_hid) + b_hid ; X = concat(map_design, goal) NHWC
// grid 512 = (b*32 + y), 128 threads = output channel
// ---------------------------------------------------------------------------
__global__ __launch_bounds__(128) void k_hid(
    const float* __restrict__ mapd, const float* __restrict__ goal,
    const float* __restrict__ W, const float* __restrict__ bias)
{
    __shared__ float shx[3 * 34 * 2];
    const int blk = blockIdx.x;
    const int b = blk >> 5, y = blk & 31;
    const int tid = threadIdx.x;

    for (int i = tid; i < 3 * 34 * 2; i += 128) {
        int r = i / 68, rem = i - r * 68;
        int xx = rem >> 1, ci = rem & 1;
        int yy = y + r - 1;
        float v = 0.0f;
        if (yy >= 0 && yy < 32 && xx >= 1 && xx <= 32) {
            int idx = b * 1024 + yy * 32 + (xx - 1);
            v = ci ? goal[idx] : mapd[idx];
        }
        shx[i] = v;
    }
    __syncthreads();

    const int c = tid;
    float w[18];
#pragma unroll
    for (int t = 0; t < 18; ++t) w[t] = W[t * 128 + c];

    float acc[32];
#pragma unroll
    for (int x = 0; x < 32; ++x) acc[x] = 0.0f;

#pragma unroll
    for (int tap = 0; tap < 9; ++tap) {
        int base = ((tap / 3) * 34 + (tap % 3)) * 2;
#pragma unroll
        for (int x = 0; x < 32; ++x) {
            acc[x] += shx[base + x * 2]     * w[tap * 2];
            acc[x] += shx[base + x * 2 + 1] * w[tap * 2 + 1];
        }
    }
    float bb = bias[c];
    int p0 = blk * 32;
#pragma unroll
    for (int x = 0; x < 32; ++x)
        g_hid[(p0 + x) * 128 + c] = acc[x] + bb;
}

// ---------------------------------------------------------------------------
// Kernel 2: h0 = conv3x3(hid, W_h0)+b ; c0 = conv3x3(hid, W_c0)+b
// grid 512 rows, 128 threads = channel (each thread computes both outputs, 32 px)
// dyn smem: shH[3][34][128] + shWh[128*33] + shWc[128*33]
// ---------------------------------------------------------------------------
__global__ __launch_bounds__(128) void k_h0c0(
    const float* __restrict__ Wh, const float* __restrict__ bh,
    const float* __restrict__ Wc, const float* __restrict__ bc)
{
    extern __shared__ float sm[];
    float* shH  = sm;                  // 13056 floats
    float* shWh = sm + 13056;          // 4224
    float* shWc = shWh + 4224;         // 4224

    const int blk = blockIdx.x;
    const int b = blk >> 5, y = blk & 31;
    const int tid = threadIdx.x;

    // Load 3 rows of hid (zero-padded) as float4
    {
        const float4* src4 = (const float4*)g_hid;
        float4* sh4 = (float4*)shH;
        for (int i = tid; i < 3 * 34 * 32; i += 128) {
            int r = i / (34 * 32);
            int rem = i - r * (34 * 32);
            int xx = rem >> 5, k4 = rem & 31;
            int yy = y + r - 1;
            float4 v = make_float4(0.f, 0.f, 0.f, 0.f);
            if (yy >= 0 && yy < 32 && xx >= 1 && xx <= 32)
                v = src4[((b * 32 + yy) * 32 + (xx - 1)) * 32 + k4];
            sh4[i] = v;
        }
    }

    const int c = tid;
    float accH[32], accC[32];
#pragma unroll
    for (int x = 0; x < 32; ++x) { accH[x] = 0.0f; accC[x] = 0.0f; }

    for (int tap = 0; tap < 9; ++tap) {
        const int r = tap / 3;
        const int dxp = tap % 3;
#pragma unroll 1
        for (int kc = 0; kc < 4; ++kc) {
            __syncthreads();
            // Stage weight chunk [32k x 128c] for both convs (conflict-free layout)
            for (int i = tid; i < 4096; i += 128) {
                int k = i >> 7, cc = i & 127;
                int gidx = (tap * 128 + kc * 32 + k) * 128 + cc;
                shWh[cc * 33 + k] = Wh[gidx];
                shWc[cc * 33 + k] = Wc[gidx];
            }
            __syncthreads();
#pragma unroll 2
            for (int k4 = 0; k4 < 8; ++k4) {
                const float* wph = &shWh[c * 33 + k4 * 4];
                const float* wpc = &shWc[c * 33 + k4 * 4];
                float wh0 = wph[0], wh1 = wph[1], wh2 = wph[2], wh3 = wph[3];
                float wc0 = wpc[0], wc1 = wpc[1], wc2 = wpc[2], wc3 = wpc[3];
#pragma unroll
                for (int x = 0; x < 32; ++x) {
                    const float4 v = *(const float4*)&shH[(r * 34 + x + dxp) * 128 + kc * 32 + k4 * 4];
                    accH[x] += v.x * wh0; accH[x] += v.y * wh1;
                    accH[x] += v.z * wh2; accH[x] += v.w * wh3;
                    accC[x] += v.x * wc0; accC[x] += v.y * wc1;
                    accC[x] += v.z * wc2; accC[x] += v.w * wc3;
                }
            }
        }
    }

    float bbh = bh[c], bbc = bc[c];
    int p0 = blk * 32;
#pragma unroll
    for (int x = 0; x < 32; ++x) {
        g_hbuf[0][(p0 + x) * 128 + c] = accH[x] + bbh;
        g_cbuf[0][(p0 + x) * 128 + c] = accC[x] + bbc;
    }
}

// ---------------------------------------------------------------------------
// Kernel 3: one LSTM step, fully fused:
//   inp = conv3x3(h, W_f)+b_f (per-pixel scalar)
//   gates = inp*W_ih + b_ih + h @ W_hh^T + b_hh ; LSTM pointwise update
// grid 512 rows, 256 threads. Thread tile: 8 px x 2 j x 4 gates.
// dyn smem: shH[3][34][128] + shW[512*33] + shInp[32]
// ---------------------------------------------------------------------------
__global__ __launch_bounds__(256) void k_step(
    const float* __restrict__ Wf,  const float* __restrict__ bf,
    const float* __restrict__ Wih, const float* __restrict__ bih,
    const float* __restrict__ Whh, const float* __restrict__ bhh,
    int rb)
{
    extern __shared__ float sm[];
    float* shH   = sm;                 // 13056
    float* shW   = sm + 13056;         // 16896
    float* shInp = shW + 16896;        // 32

    const int blk = blockIdx.x;
    const int b = blk >> 5, y = blk & 31;
    const int tid = threadIdx.x;

    // Load 3 rows of h (prev step), zero-padded
    {
        const float4* src4 = (const float4*)g_hbuf[rb];
        float4* sh4 = (float4*)shH;
        for (int i = tid; i < 3 * 34 * 32; i += 256) {
            int r = i / (34 * 32);
            int rem = i - r * (34 * 32);
            int xx = rem >> 5, k4 = rem & 31;
            int yy = y + r - 1;
            float4 v = make_float4(0.f, 0.f, 0.f, 0.f);
            if (yy >= 0 && yy < 32 && xx >= 1 && xx <= 32)
                v = src4[((b * 32 + yy) * 32 + (xx - 1)) * 32 + k4];
            sh4[i] = v;
        }
    }
    __syncthreads();

    // conv_f: 8 partial threads per pixel, shfl-reduce
    {
        int x = tid >> 3, part = tid & 7;
        float s = 0.0f;
        const float4* Wf4 = (const float4*)Wf;
#pragma unroll
        for (int tap = 0; tap < 9; ++tap) {
            const float4* h4 = (const float4*)&shH[((tap / 3) * 34 + x + (tap % 3)) * 128 + part * 16];
#pragma unroll
            for (int k4 = 0; k4 < 4; ++k4) {
                float4 w = Wf4[tap * 32 + part * 4 + k4];
                float4 h = h4[k4];
                s += h.x * w.x; s += h.y * w.y; s += h.z * w.z; s += h.w * w.w;
            }
        }
        s += __shfl_down_sync(0xffffffffu, s, 4, 8);
        s += __shfl_down_sync(0xffffffffu, s, 2, 8);
        s += __shfl_down_sync(0xffffffffu, s, 1, 8);
        if (part == 0) shInp[x] = s + bf[0];
    }

    // GEMM: gates accumulation, W_hh staged through smem in 4 k-chunks
    const int jg = tid & 63;
    const int pg = tid >> 6;
    const int xb = pg * 8;

    float acc[64];
#pragma unroll
    for (int i = 0; i < 64; ++i) acc[i] = 0.0f;

#pragma unroll 1
    for (int kc = 0; kc < 4; ++kc) {
        __syncthreads();
        for (int i = tid; i < 4096; i += 256) {
            int row = i >> 3, k4 = i & 7;
            const float4 v = *(const float4*)&Whh[row * 128 + kc * 32 + k4 * 4];
            float* d = &shW[row * 33 + k4 * 4];
            d[0] = v.x; d[1] = v.y; d[2] = v.z; d[3] = v.w;
        }
        __syncthreads();
#pragma unroll 2
        for (int k4 = 0; k4 < 8; ++k4) {
            float w[32];
#pragma unroll
            for (int a = 0; a < 2; ++a)
#pragma unroll
                for (int g = 0; g < 4; ++g) {
                    int row = g * 128 + jg + a * 64;
                    const float* wp = &shW[row * 33 + k4 * 4];
                    w[(a * 4 + g) * 4 + 0] = wp[0];
                    w[(a * 4 + g) * 4 + 1] = wp[1];
                    w[(a * 4 + g) * 4 + 2] = wp[2];
                    w[(a * 4 + g) * 4 + 3] = wp[3];
                }
#pragma unroll
            for (int px = 0; px < 8; ++px) {
                const float4 hv = *(const float4*)&shH[(34 + xb + px + 1) * 128 + kc * 32 + k4 * 4];
#pragma unroll
                for (int a = 0; a < 2; ++a)
#pragma unroll
                    for (int g = 0; g < 4; ++g) {
                        const int ai = (a * 4 + g) * 8 + px;
                        const float* ww = &w[(a * 4 + g) * 4];
                        acc[ai] += hv.x * ww[0];
                        acc[ai] += hv.y * ww[1];
                        acc[ai] += hv.z * ww[2];
                        acc[ai] += hv.w * ww[3];
                    }
            }
        }
    }

    // Epilogue: LSTM pointwise update
    const int wb = rb ^ 1;
    const float* cOld = g_cbuf[rb];
    float* cNew = g_cbuf[wb];
    float* hNew = g_hbuf[wb];

#pragma unroll
    for (int a = 0; a < 2; ++a) {
        const int j = jg + a * 64;
        float wi[4], bi[4];
#pragma unroll
        for (int g = 0; g < 4; ++g) {
            int row = g * 128 + j;
            wi[g] = Wih[row];
            bi[g] = bih[row] + bhh[row];
        }
#pragma unroll
        for (int px = 0; px < 8; ++px) {
            const int p = blk * 32 + xb + px;
            const float inp = shInp[xb + px];
            float gi = acc[(a * 4 + 0) * 8 + px] + inp * wi[0] + bi[0];
            float gf = acc[(a * 4 + 1) * 8 + px] + inp * wi[1] + bi[1];
            float gg = acc[(a * 4 + 2) * 8 + px] + inp * wi[2] + bi[2];
            float go = acc[(a * 4 + 3) * 8 + px] + inp * wi[3] + bi[3];
            float iv = sigf(gi), fv = sigf(gf), gv = tanhx(gg), ov = sigf(go);
            float cn = fv * cOld[p * 128 + j] + iv * gv;
            cNew[p * 128 + j] = cn;
            hNew[p * 128 + j] = ov * tanhx(cn);
        }
    }
}

// ---------------------------------------------------------------------------
// Kernel 4: policy 1x1 conv + softmax over NA=4; write logits then probs
// grid 256 blocks x 64 px, 256 threads (4 partial threads / pixel)
// ---------------------------------------------------------------------------
__global__ __launch_bounds__(256) void k_policy(
    const float* __restrict__ Wpol, float* __restrict__ out)
{
    __shared__ float shH[64 * 128];
    const int blk = blockIdx.x, tid = threadIdx.x;
    const int p0 = blk * 64;

    {
        const float4* src4 = (const float4*)g_hbuf[NSTEPS & 1];
        float4* sh4 = (float4*)shH;
        for (int i = tid; i < 64 * 32; i += 256)
            sh4[i] = src4[p0 * 32 + i];
    }
    __syncthreads();

    const int px = tid >> 2, q = tid & 3;
    const float4* W4 = (const float4*)Wpol;
    float ax = 0.f, ay = 0.f, az = 0.f, aw = 0.f;
#pragma unroll
    for (int k = q * 32; k < q * 32 + 32; ++k) {
        float hv = shH[px * 128 + k];
        float4 w = W4[k];
        ax += hv * w.x; ay += hv * w.y; az += hv * w.z; aw += hv * w.w;
    }
    ax += __shfl_down_sync(0xffffffffu, ax, 2, 4);
    ay += __shfl_down_sync(0xffffffffu, ay, 2, 4);
    az += __shfl_down_sync(0xffffffffu, az, 2, 4);
    aw += __shfl_down_sync(0xffffffffu, aw, 2, 4);
    ax += __shfl_down_sync(0xffffffffu, ax, 1, 4);
    ay += __shfl_down_sync(0xffffffffu, ay, 1, 4);
    az += __shfl_down_sync(0xffffffffu, az, 1, 4);
    aw += __shfl_down_sync(0xffffffffu, aw, 1, 4);

    if (q == 0) {
        const int p = p0 + px;
        const int b = p >> 10, rem = p & 1023;
        float m = fmaxf(fmaxf(ax, ay), fmaxf(az, aw));
        float e0 = __expf(ax - m), e1 = __expf(ay - m);
        float e2 = __expf(az - m), e3 = __expf(aw - m);
        float inv = __fdividef(1.0f, e0 + e1 + e2 + e3);
        const int base = b * 4096 + rem;
        out[base]            = ax;
        out[base + 1024]     = ay;
        out[base + 2048]     = az;
        out[base + 3072]     = aw;
        float* pr = out + 65536;
        pr[base]            = e0 * inv;
        pr[base + 1024]     = e1 * inv;
        pr[base + 2048]     = e2 * inv;
        pr[base + 3072]     = e3 * inv;
    }
}

// ---------------------------------------------------------------------------
extern "C" void kernel_launch(void* const* d_in, const int* in_sizes, int n_in,
                              void* d_out, int out_size)
{
    (void)in_sizes; (void)n_in; (void)out_size;
    const float* mapd  = (const float*)d_in[0];
    const float* goal  = (const float*)d_in[1];
    const float* W_hid = (const float*)d_in[2];
    const float* b_hid = (const float*)d_in[3];
    const float* W_h0  = (const float*)d_in[4];
    const float* b_h0  = (const float*)d_in[5];
    const float* W_c0  = (const float*)d_in[6];
    const float* b_c0  = (const float*)d_in[7];
    const float* W_f   = (const float*)d_in[8];
    const float* b_f   = (const float*)d_in[9];
    const float* W_ih  = (const float*)d_in[10];
    const float* b_ih  = (const float*)d_in[11];
    const float* W_hh  = (const float*)d_in[12];
    const float* b_hh  = (const float*)d_in[13];
    const float* W_pol = (const float*)d_in[14];
    float* out = (float*)d_out;

    const int smem2 = (13056 + 4224 * 2) * 4;          // 86016 B
    const int smem3 = (13056 + 16896 + 32) * 4;        // 119936 B
    cudaFuncSetAttribute(k_h0c0, cudaFuncAttributeMaxDynamicSharedMemorySize, smem2);
    cudaFuncSetAttribute(k_step, cudaFuncAttributeMaxDynamicSharedMemorySize, smem3);

    k_hid<<<512, 128>>>(mapd, goal, W_hid, b_hid);
    k_h0c0<<<512, 128, smem2>>>(W_h0, b_h0, W_c0, b_c0);
    for (int s = 0; s < NSTEPS; ++s)
        k_step<<<512, 256, smem3>>>(W_f, b_f, W_ih, b_ih, W_hh, b_hh, s & 1);
    k_policy<<<256, 256>>>(W_pol, out);
}

// round 6
// speedup vs baseline: 2.3432x; 2.3432x over previous
#include <cuda_runtime.h>
#include <cuda_bf16.h>
#include <cstdint>

#define NB 16
#define NM 32
#define NLH 128
#define NSTEPS 15
#define NPIX (NB*NM*NM)

// ---------------- scratch (static __device__; no cudaMalloc allowed) --------
__device__ float g_hid[NPIX*NLH];                 // [pixel][k] fp32
__device__ float g_c[2][NLH*NPIX];                // [j][pixel] fp32, double buffered
__device__ __nv_bfloat16 g_h_hi[NLH*NPIX];        // [j][pixel] bf16 hi
__device__ __nv_bfloat16 g_h_lo[NLH*NPIX];        // [j][pixel] bf16 lo
__device__ float g_inp[NPIX];                     // conv_f output per pixel
__device__ __align__(16) char g_wblob[262144];    // Whh bf16 hi/lo, permuted+swizzled

__device__ __forceinline__ float sigf(float x) {
    return __fdividef(1.0f, 1.0f + __expf(-x));
}
__device__ __forceinline__ float tanhx(float x) {
    return __fdividef(2.0f, 1.0f + __expf(-2.0f * x)) - 1.0f;
}

__device__ __forceinline__ uint32_t s2u(const void* p) {
    uint32_t a;
    asm("{ .reg .u64 t; cvta.to.shared.u64 t, %1; cvt.u32.u64 %0, t; }" : "=r"(a) : "l"(p));
    return a;
}

#define LDSM4(r, a) \
    asm volatile("ldmatrix.sync.aligned.m8n8.x4.shared.b16 {%0,%1,%2,%3}, [%4];" \
        : "=r"((r)[0]), "=r"((r)[1]), "=r"((r)[2]), "=r"((r)[3]) : "r"(a))
#define LDSM4T(r, a) \
    asm volatile("ldmatrix.sync.aligned.m8n8.x4.trans.shared.b16 {%0,%1,%2,%3}, [%4];" \
        : "=r"((r)[0]), "=r"((r)[1]), "=r"((r)[2]), "=r"((r)[3]) : "r"(a))

__device__ __forceinline__ void mma_bf16(float* d, const uint32_t* a, const uint32_t b0, const uint32_t b1) {
    asm volatile(
        "mma.sync.aligned.m16n8k16.row.col.f32.bf16.bf16.f32 "
        "{%0,%1,%2,%3},{%4,%5,%6,%7},{%8,%9},{%0,%1,%2,%3};"
        : "+f"(d[0]), "+f"(d[1]), "+f"(d[2]), "+f"(d[3])
        : "r"(a[0]), "r"(a[1]), "r"(a[2]), "r"(a[3]), "r"(b0), "r"(b1));
}

#define CPASYNC16(s, g) asm volatile("cp.async.cg.shared.global [%0], [%1], 16;" :: "r"(s), "l"(g))
#define CPCOMMIT()      asm volatile("cp.async.commit_group;" ::: "memory")
#define CPWAIT(n)       asm volatile("cp.async.wait_group %0;" :: "n"(n) : "memory")

// smem layout (bytes) for k_step_mma
#define SM_A      0        // A^T hi (32KB) + lo (32KB); row=k (256B), col=px
#define SM_B      65536    // 2 bufs x 64KB (hi 32KB + lo 32KB each)
#define OFF_WIH   196608   // 512 floats
#define OFF_BIAS  198656   // 512 floats
#define SMEM_STEP 200704

// ---------------------------------------------------------------------------
// k_prep: Whh fp32 -> permuted (n = j_loc*4+gate per 32-j chunk), swizzled bf16
// blob layout: [ch 0..3][hl 0..1][n_loc 0..127][k 0..127]
//   byte = ch*65536 + hl*32768 + n*256 + ((k*2) ^ ((n&7)<<4))
// ---------------------------------------------------------------------------
__global__ __launch_bounds__(256) void k_prep(const float* __restrict__ Whh)
{
    int idx = blockIdx.x * 256 + threadIdx.x;
    if (idx >= 131072) return;
    int ch = idx >> 15;
    int hl = (idx >> 14) & 1;
    int n  = (idx >> 7) & 127;
    int k  = idx & 127;
    int j_loc = n >> 2, gate = n & 3;
    int grow = gate * 128 + ch * 32 + j_loc;
    float w = Whh[grow * 128 + k];
    __nv_bfloat16 hi = __float2bfloat16(w);
    __nv_bfloat16 val = hl ? __float2bfloat16(w - __bfloat162float(hi)) : hi;
    int off = ch * 65536 + hl * 32768 + n * 256 + ((k * 2) ^ ((n & 7) << 4));
    *(__nv_bfloat16*)(g_wblob + off) = val;
}

// ---------------------------------------------------------------------------
// k_hid (unchanged; writes g_hid [pixel][k])
// ---------------------------------------------------------------------------
__global__ __launch_bounds__(128) void k_hid(
    const float* __restrict__ mapd, const float* __restrict__ goal,
    const float* __restrict__ W, const float* __restrict__ bias)
{
    __shared__ float shx[3 * 34 * 2];
    const int blk = blockIdx.x;
    const int b = blk >> 5, y = blk & 31;
    const int tid = threadIdx.x;

    for (int i = tid; i < 3 * 34 * 2; i += 128) {
        int r = i / 68, rem = i - r * 68;
        int xx = rem >> 1, ci = rem & 1;
        int yy = y + r - 1;
        float v = 0.0f;
        if (yy >= 0 && yy < 32 && xx >= 1 && xx <= 32) {
            int idx = b * 1024 + yy * 32 + (xx - 1);
            v = ci ? goal[idx] : mapd[idx];
        }
        shx[i] = v;
    }
    __syncthreads();

    const int c = tid;
    float w[18];
#pragma unroll
    for (int t = 0; t < 18; ++t) w[t] = W[t * 128 + c];

    float acc[32];
#pragma unroll
    for (int x = 0; x < 32; ++x) acc[x] = 0.0f;

#pragma unroll
    for (int tap = 0; tap < 9; ++tap) {
        int base = ((tap / 3) * 34 + (tap % 3)) * 2;
#pragma unroll
        for (int x = 0; x < 32; ++x) {
            acc[x] += shx[base + x * 2]     * w[tap * 2];
            acc[x] += shx[base + x * 2 + 1] * w[tap * 2 + 1];
        }
    }
    float bb = bias[c];
    int p0 = blk * 32;
#pragma unroll
    for (int x = 0; x < 32; ++x)
        g_hid[(p0 + x) * 128 + c] = acc[x] + bb;
}

// ---------------------------------------------------------------------------
// k_h0c0: fp32 conv; c0 -> g_c[0] [j][p]; h0 -> g_h_hi/lo [j][p]
// ---------------------------------------------------------------------------
__global__ __launch_bounds__(128) void k_h0c0(
    const float* __restrict__ Wh, const float* __restrict__ bh,
    const float* __restrict__ Wc, const float* __restrict__ bc)
{
    extern __shared__ float sm[];
    float* shH  = sm;                  // 13056 floats
    float* shWh = sm + 13056;          // 4224
    float* shWc = shWh + 4224;         // 4224

    const int blk = blockIdx.x;
    const int b = blk >> 5, y = blk & 31;
    const int tid = threadIdx.x;

    {
        const float4* src4 = (const float4*)g_hid;
        float4* sh4 = (float4*)shH;
        for (int i = tid; i < 3 * 34 * 32; i += 128) {
            int r = i / (34 * 32);
            int rem = i - r * (34 * 32);
            int xx = rem >> 5, k4 = rem & 31;
            int yy = y + r - 1;
            float4 v = make_float4(0.f, 0.f, 0.f, 0.f);
            if (yy >= 0 && yy < 32 && xx >= 1 && xx <= 32)
                v = src4[((b * 32 + yy) * 32 + (xx - 1)) * 32 + k4];
            sh4[i] = v;
        }
    }

    const int c = tid;
    float accH[32], accC[32];
#pragma unroll
    for (int x = 0; x < 32; ++x) { accH[x] = 0.0f; accC[x] = 0.0f; }

    for (int tap = 0; tap < 9; ++tap) {
        const int r = tap / 3;
        const int dxp = tap % 3;
#pragma unroll 1
        for (int kc = 0; kc < 4; ++kc) {
            __syncthreads();
            for (int i = tid; i < 4096; i += 128) {
                int k = i >> 7, cc = i & 127;
                int gidx = (tap * 128 + kc * 32 + k) * 128 + cc;
                shWh[cc * 33 + k] = Wh[gidx];
                shWc[cc * 33 + k] = Wc[gidx];
            }
            __syncthreads();
#pragma unroll 2
            for (int k4 = 0; k4 < 8; ++k4) {
                const float* wph = &shWh[c * 33 + k4 * 4];
                const float* wpc = &shWc[c * 33 + k4 * 4];
                float wh0 = wph[0], wh1 = wph[1], wh2 = wph[2], wh3 = wph[3];
                float wc0 = wpc[0], wc1 = wpc[1], wc2 = wpc[2], wc3 = wpc[3];
#pragma unroll
                for (int x = 0; x < 32; ++x) {
                    const float4 v = *(const float4*)&shH[(r * 34 + x + dxp) * 128 + kc * 32 + k4 * 4];
                    accH[x] += v.x * wh0; accH[x] += v.y * wh1;
                    accH[x] += v.z * wh2; accH[x] += v.w * wh3;
                    accC[x] += v.x * wc0; accC[x] += v.y * wc1;
                    accC[x] += v.z * wc2; accC[x] += v.w * wc3;
                }
            }
        }
    }

    float bbh = bh[c], bbc = bc[c];
    int p0 = blk * 32;
#pragma unroll
    for (int x = 0; x < 32; ++x) {
        int p = p0 + x;
        g_c[0][c * NPIX + p] = accC[x] + bbc;
        float hv = accH[x] + bbh;
        __nv_bfloat16 hi = __float2bfloat16(hv);
        __nv_bfloat16 lo = __float2bfloat16(hv - __bfloat162float(hi));
        g_h_hi[c * NPIX + p] = hi;
        g_h_lo[c * NPIX + p] = lo;
    }
}

// ---------------------------------------------------------------------------
// k_convf: inp[pixel] = conv3x3(h, W_f) + b_f. Reads h [j][p] bf16 hi/lo.
// ---------------------------------------------------------------------------
__global__ __launch_bounds__(128) void k_convf(
    const float* __restrict__ Wf, const float* __restrict__ bf)
{
    extern __shared__ float sm[];
    float* X   = sm;            // 128*109 = 13952
    float* sWf = sm + 13952;    // 1152

    const int blk = blockIdx.x;
    const int b = blk >> 5, y = blk & 31;
    const int tid = threadIdx.x;

    for (int i = tid; i < 1152; i += 128) sWf[i] = Wf[i];

    for (int u = tid; u < 128 * 12; u += 128) {
        int k = u / 12, rem = u % 12;
        int r = rem >> 2, q = rem & 3;
        int yy = y + r - 1;
        float* dst = &X[k * 109 + r * 36 + 1 + q * 8];
        if (yy >= 0 && yy < 32) {
            uint4 hv = *(const uint4*)&g_h_hi[k * NPIX + b * 1024 + yy * 32 + q * 8];
            uint4 lv = *(const uint4*)&g_h_lo[k * NPIX + b * 1024 + yy * 32 + q * 8];
            const __nv_bfloat16* he = (const __nv_bfloat16*)&hv;
            const __nv_bfloat16* le = (const __nv_bfloat16*)&lv;
#pragma unroll
            for (int e = 0; e < 8; ++e)
                dst[e] = __bfloat162float(he[e]) + __bfloat162float(le[e]);
        } else {
#pragma unroll
            for (int e = 0; e < 8; ++e) dst[e] = 0.0f;
        }
    }
    for (int u = tid; u < 384; u += 128) {
        int k = u / 3, r = u % 3;
        X[k * 109 + r * 36] = 0.0f;
        X[k * 109 + r * 36 + 33] = 0.0f;
    }
    __syncthreads();

    const int x = tid >> 2, part = tid & 3;
    float s = 0.0f;
#pragma unroll 4
    for (int kk = 0; kk < 32; ++kk) {
        int k = part * 32 + kk;
#pragma unroll
        for (int tap = 0; tap < 9; ++tap) {
            int r = tap / 3, dx = tap % 3;
            s += X[k * 109 + r * 36 + x + dx] * sWf[tap * 128 + k];
        }
    }
    s += __shfl_down_sync(0xffffffffu, s, 2, 4);
    s += __shfl_down_sync(0xffffffffu, s, 1, 4);
    if (part == 0) g_inp[b * 1024 + y * 32 + x] = s + bf[0];
}

// ---------------------------------------------------------------------------
// k_step_mma: HMMA bf16 hi/lo-split GEMM + fused LSTM epilogue.
// 128 CTAs x 256 threads; M=128 px, N=512 (4 chunks of 128), K=128.
// ---------------------------------------------------------------------------
struct TileCtx {
    uint32_t smb;
    uint32_t offA0, offA1;   // lane-dependent A offsets (mf0/mf1), pass-hi base
    uint32_t kB2;            // lane k-offset for B (bytes)
    int mt, lane, mf;
    int pixA, pixB;
    float inpA, inpB;
    const float* sWih;
    const float* sBias;
    const float* cOld;
    float* cNew;
};

__device__ __forceinline__ void do_tile(const TileCtx& T, int ch, int nt, uint32_t Bbase)
{
    const int lane = T.lane;
    float acc[2][4][4];
#pragma unroll
    for (int m = 0; m < 2; ++m)
#pragma unroll
        for (int n = 0; n < 4; ++n)
#pragma unroll
            for (int k = 0; k < 4; ++k) acc[m][n][k] = 0.0f;

    const int nrow0 = nt * 32 + (lane & 7) + (((lane >> 3) & 1) << 3);
    const uint32_t swz0 = (nrow0 & 7) << 4;
    const uint32_t pbase0 = nrow0 * 256;
    const uint32_t pbase1 = (nrow0 + 16) * 256;

#pragma unroll
    for (int pass = 0; pass < 3; ++pass) {
        uint32_t Ab = T.smb + SM_A + ((pass == 1) ? 32768 : 0);
        uint32_t Bb = Bbase + ((pass == 2) ? 32768 : 0);
        uint32_t pa0 = Ab + T.offA0;
        uint32_t pa1 = Ab + T.offA1;
        uint32_t pb0 = Bb + pbase0;
        uint32_t pb1 = Bb + pbase1;
#pragma unroll
        for (int ks = 0; ks < 8; ++ks) {
            uint32_t a0[4], a1[4], r0[4], r1[4];
            LDSM4T(a0, pa0);
            LDSM4T(a1, pa1);
            uint32_t kb2 = (uint32_t)(ks * 32) + T.kB2;
            LDSM4(r0, pb0 + (kb2 ^ swz0));
            LDSM4(r1, pb1 + (kb2 ^ swz0));
            mma_bf16(acc[0][0], a0, r0[0], r0[2]);
            mma_bf16(acc[0][1], a0, r0[1], r0[3]);
            mma_bf16(acc[0][2], a0, r1[0], r1[2]);
            mma_bf16(acc[0][3], a0, r1[1], r1[3]);
            mma_bf16(acc[1][0], a1, r0[0], r0[2]);
            mma_bf16(acc[1][1], a1, r0[1], r0[3]);
            mma_bf16(acc[1][2], a1, r1[0], r1[2]);
            mma_bf16(acc[1][3], a1, r1[1], r1[3]);
            pa0 += 4096; pa1 += 4096;
        }
    }

    // ---- fused LSTM epilogue ----
    const int jbase = ch * 32 + nt * 8 + ((lane & 3) >> 1);
#pragma unroll
    for (int nf = 0; nf < 4; ++nf) {
        float send[4], recv[4];
#pragma unroll
        for (int k = 0; k < 4; ++k)
            send[k] = T.mf ? acc[0][nf][k] : acc[1][nf][k];
#pragma unroll
        for (int k = 0; k < 4; ++k)
            recv[k] = __shfl_xor_sync(0xffffffffu, send[k], 1);

        float i1, f1, g1, o1, i2, f2, g2, o2;
        if (T.mf == 0) {
            i1 = acc[0][nf][0]; f1 = acc[0][nf][1];
            i2 = acc[0][nf][2]; f2 = acc[0][nf][3];
            g1 = recv[0]; o1 = recv[1]; g2 = recv[2]; o2 = recv[3];
        } else {
            g1 = acc[1][nf][0]; o1 = acc[1][nf][1];
            g2 = acc[1][nf][2]; o2 = acc[1][nf][3];
            i1 = recv[0]; f1 = recv[1]; i2 = recv[2]; f2 = recv[3];
        }
        const int j = jbase + nf * 2;
        const float wii = T.sWih[j],        wif = T.sWih[128 + j];
        const float wig = T.sWih[256 + j],  wio = T.sWih[384 + j];
        const float bi  = T.sBias[j],       bff = T.sBias[128 + j];
        const float bg  = T.sBias[256 + j], bo  = T.sBias[384 + j];
        const long jbaseN = (long)j * NPIX;

        {
            float gi = i1 + T.inpA * wii + bi;
            float gf = f1 + T.inpA * wif + bff;
            float gg = g1 + T.inpA * wig + bg;
            float go = o1 + T.inpA * wio + bo;
            float cn = sigf(gf) * T.cOld[jbaseN + T.pixA] + sigf(gi) * tanhx(gg);
            T.cNew[jbaseN + T.pixA] = cn;
            float hv = sigf(go) * tanhx(cn);
            __nv_bfloat16 hi = __float2bfloat16(hv);
            g_h_hi[jbaseN + T.pixA] = hi;
            g_h_lo[jbaseN + T.pixA] = __float2bfloat16(hv - __bfloat162float(hi));
        }
        {
            float gi = i2 + T.inpB * wii + bi;
            float gf = f2 + T.inpB * wif + bff;
            float gg = g2 + T.inpB * wig + bg;
            float go = o2 + T.inpB * wio + bo;
            float cn = sigf(gf) * T.cOld[jbaseN + T.pixB] + sigf(gi) * tanhx(gg);
            T.cNew[jbaseN + T.pixB] = cn;
            float hv = sigf(go) * tanhx(cn);
            __nv_bfloat16 hi = __float2bfloat16(hv);
            g_h_hi[jbaseN + T.pixB] = hi;
            g_h_lo[jbaseN + T.pixB] = __float2bfloat16(hv - __bfloat162float(hi));
        }
    }
}

__global__ __launch_bounds__(256) void k_step_mma(
    const float* __restrict__ Wih, const float* __restrict__ bih,
    const float* __restrict__ bhh, int rb)
{
    extern __shared__ char smc[];
    const int tid = threadIdx.x;
    const int warp = tid >> 5, lane = tid & 31;
    const int blk = blockIdx.x;
    const int P0 = blk * 128;
    const uint32_t smb = s2u(smc);

    // ---- issue async B copies for chunks 0, 1 ----
    {
        const char* src = g_wblob;
        for (int i = tid; i < 4096; i += 256)
            CPASYNC16(smb + SM_B + i * 16, src + i * 16);
        CPCOMMIT();
        for (int i = tid; i < 4096; i += 256)
            CPASYNC16(smb + SM_B + 65536 + i * 16, src + 65536 + i * 16);
        CPCOMMIT();
    }

    // ---- stage A^T hi/lo: row=k (256B swizzled), col=px ----
    for (int c = tid; c < 2048; c += 256) {
        int k = c >> 4, pc = c & 15;
        uint4 hv = *(const uint4*)&g_h_hi[k * NPIX + P0 + pc * 8];
        uint4 lv = *(const uint4*)&g_h_lo[k * NPIX + P0 + pc * 8];
        uint32_t off = (uint32_t)(k * 256) + (((uint32_t)(pc * 16)) ^ ((uint32_t)((k & 7) << 4)));
        *(uint4*)(smc + SM_A + off) = hv;
        *(uint4*)(smc + SM_A + 32768 + off) = lv;
    }

    // ---- stage gate constants ----
    {
        float* sWih = (float*)(smc + OFF_WIH);
        float* sBias = (float*)(smc + OFF_BIAS);
        for (int i = tid; i < 512; i += 256) {
            sWih[i] = Wih[i];
            sBias[i] = bih[i] + bhh[i];
        }
    }

    // ---- per-warp / per-lane constants ----
    TileCtx T;
    T.smb = smb;
    T.lane = lane;
    T.mt = warp & 3;
    T.mf = lane & 1;
    {
        int kA = (lane & 7) + ((lane >> 4) << 3);
        int pxg = ((lane >> 3) & 1) << 3;
        int px0 = T.mt * 32 + pxg;
        uint32_t swzA = (kA & 7) << 4;
        T.offA0 = (uint32_t)(kA * 256) + (((uint32_t)(px0 * 2)) ^ swzA);
        T.offA1 = (uint32_t)(kA * 256) + (((uint32_t)((px0 + 16) * 2)) ^ swzA);
        T.kB2 = (uint32_t)((lane >> 4) << 4);
    }
    {
        int r = lane >> 2;
        T.pixA = P0 + T.mt * 32 + T.mf * 16 + r;
        T.pixB = T.pixA + 8;
        T.inpA = g_inp[T.pixA];
        T.inpB = g_inp[T.pixB];
    }
    T.sWih = (const float*)(smc + OFF_WIH);
    T.sBias = (const float*)(smc + OFF_BIAS);
    T.cOld = g_c[rb];
    T.cNew = g_c[rb ^ 1];

    const int ntg = warp >> 2;   // 0 or 1 -> n-tiles {2*ntg, 2*ntg+1} per chunk

    CPWAIT(1);
    __syncthreads();   // buf0 + A + consts ready

    // chunk 0 (buf0)
    do_tile(T, 0, ntg * 2 + 0, smb + SM_B);
    do_tile(T, 0, ntg * 2 + 1, smb + SM_B);
    __syncthreads();   // everyone done with buf0
    {
        const char* src = g_wblob + 2 * 65536;
        for (int i = tid; i < 4096; i += 256)
            CPASYNC16(smb + SM_B + i * 16, src + i * 16);
        CPCOMMIT();
    }
    CPWAIT(1);         // buf1 (chunk1) done
    __syncthreads();

    // chunk 1 (buf1)
    do_tile(T, 1, ntg * 2 + 0, smb + SM_B + 65536);
    do_tile(T, 1, ntg * 2 + 1, smb + SM_B + 65536);
    __syncthreads();
    {
        const char* src = g_wblob + 3 * 65536;
        for (int i = tid; i < 4096; i += 256)
            CPASYNC16(smb + SM_B + 65536 + i * 16, src + i * 16);
        CPCOMMIT();
    }
    CPWAIT(1);         // buf0 (chunk2) done
    __syncthreads();

    // chunk 2 (buf0)
    do_tile(T, 2, ntg * 2 + 0, smb + SM_B);
    do_tile(T, 2, ntg * 2 + 1, smb + SM_B);
    CPWAIT(0);         // buf1 (chunk3) done
    __syncthreads();

    // chunk 3 (buf1)
    do_tile(T, 3, ntg * 2 + 0, smb + SM_B + 65536);
    do_tile(T, 3, ntg * 2 + 1, smb + SM_B + 65536);
}

// ---------------------------------------------------------------------------
// k_policy: 1x1 conv + softmax. Reads h [j][p] bf16 hi/lo.
// ---------------------------------------------------------------------------
__global__ __launch_bounds__(256) void k_policy(
    const float* __restrict__ Wpol, float* __restrict__ out)
{
    __shared__ float shH[128 * 66];
    const int blk = blockIdx.x, tid = threadIdx.x;
    const int p0 = blk * 64;

    for (int u = tid; u < 128 * 8; u += 256) {
        int k = u >> 3, q = u & 7;
        uint4 hv = *(const uint4*)&g_h_hi[k * NPIX + p0 + q * 8];
        uint4 lv = *(const uint4*)&g_h_lo[k * NPIX + p0 + q * 8];
        const __nv_bfloat16* he = (const __nv_bfloat16*)&hv;
        const __nv_bfloat16* le = (const __nv_bfloat16*)&lv;
#pragma unroll
        for (int e = 0; e < 8; ++e)
            shH[k * 66 + q * 8 + e] = __bfloat162float(he[e]) + __bfloat162float(le[e]);
    }
    __syncthreads();

    const int px = tid >> 2, q = tid & 3;
    const float4* W4 = (const float4*)Wpol;
    float ax = 0.f, ay = 0.f, az = 0.f, aw = 0.f;
#pragma unroll
    for (int k = q * 32; k < q * 32 + 32; ++k) {
        float hv = shH[k * 66 + px];
        float4 w = W4[k];
        ax += hv * w.x; ay += hv * w.y; az += hv * w.z; aw += hv * w.w;
    }
    ax += __shfl_down_sync(0xffffffffu, ax, 2, 4);
    ay += __shfl_down_sync(0xffffffffu, ay, 2, 4);
    az += __shfl_down_sync(0xffffffffu, az, 2, 4);
    aw += __shfl_down_sync(0xffffffffu, aw, 2, 4);
    ax += __shfl_down_sync(0xffffffffu, ax, 1, 4);
    ay += __shfl_down_sync(0xffffffffu, ay, 1, 4);
    az += __shfl_down_sync(0xffffffffu, az, 1, 4);
    aw += __shfl_down_sync(0xffffffffu, aw, 1, 4);

    if (q == 0) {
        const int p = p0 + px;
        const int b = p >> 10, rem = p & 1023;
        float m = fmaxf(fmaxf(ax, ay), fmaxf(az, aw));
        float e0 = __expf(ax - m), e1 = __expf(ay - m);
        float e2 = __expf(az - m), e3 = __expf(aw - m);
        float inv = __fdividef(1.0f, e0 + e1 + e2 + e3);
        const int base = b * 4096 + rem;
        out[base]            = ax;
        out[base + 1024]     = ay;
        out[base + 2048]     = az;
        out[base + 3072]     = aw;
        float* pr = out + 65536;
        pr[base]            = e0 * inv;
        pr[base + 1024]     = e1 * inv;
        pr[base + 2048]     = e2 * inv;
        pr[base + 3072]     = e3 * inv;
    }
}

// ---------------------------------------------------------------------------
extern "C" void kernel_launch(void* const* d_in, const int* in_sizes, int n_in,
                              void* d_out, int out_size)
{
    (void)in_sizes; (void)n_in; (void)out_size;
    const float* mapd  = (const float*)d_in[0];
    const float* goal  = (const float*)d_in[1];
    const float* W_hid = (const float*)d_in[2];
    const float* b_hid = (const float*)d_in[3];
    const float* W_h0  = (const float*)d_in[4];
    const float* b_h0  = (const float*)d_in[5];
    const float* W_c0  = (const float*)d_in[6];
    const float* b_c0  = (const float*)d_in[7];
    const float* W_f   = (const float*)d_in[8];
    const float* b_f   = (const float*)d_in[9];
    const float* W_ih  = (const float*)d_in[10];
    const float* b_ih  = (const float*)d_in[11];
    const float* W_hh  = (const float*)d_in[12];
    const float* b_hh  = (const float*)d_in[13];
    const float* W_pol = (const float*)d_in[14];
    float* out = (float*)d_out;

    const int smem2 = (13056 + 4224 * 2) * 4;          // 86016 B
    const int smemf = (13952 + 1152) * 4;              // 60416 B
    cudaFuncSetAttribute(k_h0c0, cudaFuncAttributeMaxDynamicSharedMemorySize, smem2);
    cudaFuncSetAttribute(k_convf, cudaFuncAttributeMaxDynamicSharedMemorySize, smemf);
    cudaFuncSetAttribute(k_step_mma, cudaFuncAttributeMaxDynamicSharedMemorySize, SMEM_STEP);

    k_hid<<<512, 128>>>(mapd, goal, W_hid, b_hid);
    k_prep<<<512, 256>>>(W_hh);
    k_h0c0<<<512, 128, smem2>>>(W_h0, b_h0, W_c0, b_c0);
    for (int s = 0; s < NSTEPS; ++s) {
        k_convf<<<512, 128, smemf>>>(W_f, b_f);
        k_step_mma<<<128, 256, SMEM_STEP>>>(W_ih, b_ih, b_hh, s & 1);
    }
    k_policy<<<256, 256>>>(W_pol, out);
}

// round 8
// speedup vs baseline: 3.1405x; 1.3403x over previous
#include <cuda_runtime.h>
#include <cuda_bf16.h>
#include <cstdint>

#define NB 16
#define NM 32
#define NLH 128
#define NSTEPS 15
#define NPIX (NB*NM*NM)

// ---------------- scratch (static __device__; no cudaMalloc allowed) --------
__device__ float g_hid[NPIX*NLH];                 // [pixel][k] fp32
__device__ float g_c[2][NLH*NPIX];                // [j][pixel] fp32, double buffered
__device__ __nv_bfloat16 g_h_hi[2][NLH*NPIX];     // [buf][j][pixel] bf16 hi
__device__ __nv_bfloat16 g_h_lo[2][NLH*NPIX];     // [buf][j][pixel] bf16 lo
__device__ __align__(16) char g_wblob[262144];    // Whh bf16 hi/lo, permuted+swizzled

__device__ __forceinline__ float sigf(float x) {
    return __fdividef(1.0f, 1.0f + __expf(-x));
}
__device__ __forceinline__ float tanhx(float x) {
    return __fdividef(2.0f, 1.0f + __expf(-2.0f * x)) - 1.0f;
}

__device__ __forceinline__ uint32_t s2u(const void* p) {
    uint32_t a;
    asm("{ .reg .u64 t; cvta.to.shared.u64 t, %1; cvt.u32.u64 %0, t; }" : "=r"(a) : "l"(p));
    return a;
}

#define LDSM4(r, a) \
    asm volatile("ldmatrix.sync.aligned.m8n8.x4.shared.b16 {%0,%1,%2,%3}, [%4];" \
        : "=r"((r)[0]), "=r"((r)[1]), "=r"((r)[2]), "=r"((r)[3]) : "r"(a))
#define LDSM4T(r, a) \
    asm volatile("ldmatrix.sync.aligned.m8n8.x4.trans.shared.b16 {%0,%1,%2,%3}, [%4];" \
        : "=r"((r)[0]), "=r"((r)[1]), "=r"((r)[2]), "=r"((r)[3]) : "r"(a))

__device__ __forceinline__ void mma_bf16(float* d, const uint32_t* a, const uint32_t b0, const uint32_t b1) {
    asm volatile(
        "mma.sync.aligned.m16n8k16.row.col.f32.bf16.bf16.f32 "
        "{%0,%1,%2,%3},{%4,%5,%6,%7},{%8,%9},{%0,%1,%2,%3};"
        : "+f"(d[0]), "+f"(d[1]), "+f"(d[2]), "+f"(d[3])
        : "r"(a[0]), "r"(a[1]), "r"(a[2]), "r"(a[3]), "r"(b0), "r"(b1));
}

#define CPASYNC16(s, g) asm volatile("cp.async.cg.shared.global [%0], [%1], 16;" :: "r"(s), "l"(g))
#define CPCOMMIT()      asm volatile("cp.async.commit_group;" ::: "memory")
#define CPWAIT(n)       asm volatile("cp.async.wait_group %0;" :: "n"(n) : "memory")

// smem layout (bytes) for k_step_mma
#define SM_A      0        // A^T hi (32KB) + lo (32KB); row=k (256B), col=px
#define SM_B      65536    // 2 bufs x 64KB (hi 32KB + lo 32KB each)
#define SM_X      (SM_B + 65536)   // X overlay in buf1: [k][6][36] bf16 (61440B)
#define OFF_WIH   196608   // 512 floats
#define OFF_BIAS  198656   // 512 floats
#define OFF_WF    200704   // 1152 floats
#define OFF_INP   205312   // 256 floats
#define SMEM_STEP 206336

// ---------------------------------------------------------------------------
// k_prep: Whh fp32 -> permuted (n = j_loc*4+gate per 32-j chunk), swizzled bf16
// ---------------------------------------------------------------------------
__global__ __launch_bounds__(256) void k_prep(const float* __restrict__ Whh)
{
    int idx = blockIdx.x * 256 + threadIdx.x;
    if (idx >= 131072) return;
    int ch = idx >> 15;
    int hl = (idx >> 14) & 1;
    int n  = (idx >> 7) & 127;
    int k  = idx & 127;
    int j_loc = n >> 2, gate = n & 3;
    int grow = gate * 128 + ch * 32 + j_loc;
    float w = Whh[grow * 128 + k];
    __nv_bfloat16 hi = __float2bfloat16(w);
    __nv_bfloat16 val = hl ? __float2bfloat16(w - __bfloat162float(hi)) : hi;
    int off = ch * 65536 + hl * 32768 + n * 256 + ((k * 2) ^ ((n & 7) << 4));
    *(__nv_bfloat16*)(g_wblob + off) = val;
}

// ---------------------------------------------------------------------------
// k_hid (writes g_hid [pixel][k])
// ---------------------------------------------------------------------------
__global__ __launch_bounds__(128) void k_hid(
    const float* __restrict__ mapd, const float* __restrict__ goal,
    const float* __restrict__ W, const float* __restrict__ bias)
{
    __shared__ float shx[3 * 34 * 2];
    const int blk = blockIdx.x;
    const int b = blk >> 5, y = blk & 31;
    const int tid = threadIdx.x;

    for (int i = tid; i < 3 * 34 * 2; i += 128) {
        int r = i / 68, rem = i - r * 68;
        int xx = rem >> 1, ci = rem & 1;
        int yy = y + r - 1;
        float v = 0.0f;
        if (yy >= 0 && yy < 32 && xx >= 1 && xx <= 32) {
            int idx = b * 1024 + yy * 32 + (xx - 1);
            v = ci ? goal[idx] : mapd[idx];
        }
        shx[i] = v;
    }
    __syncthreads();

    const int c = tid;
    float w[18];
#pragma unroll
    for (int t = 0; t < 18; ++t) w[t] = W[t * 128 + c];

    float acc[32];
#pragma unroll
    for (int x = 0; x < 32; ++x) acc[x] = 0.0f;

#pragma unroll
    for (int tap = 0; tap < 9; ++tap) {
        int base = ((tap / 3) * 34 + (tap % 3)) * 2;
#pragma unroll
        for (int x = 0; x < 32; ++x) {
            acc[x] += shx[base + x * 2]     * w[tap * 2];
            acc[x] += shx[base + x * 2 + 1] * w[tap * 2 + 1];
        }
    }
    float bb = bias[c];
    int p0 = blk * 32;
#pragma unroll
    for (int x = 0; x < 32; ++x)
        g_hid[(p0 + x) * 128 + c] = acc[x] + bb;
}

// ---------------------------------------------------------------------------
// k_h0c0: fp32 conv; c0 -> g_c[0] [j][p]; h0 -> g_h_hi/lo[0] [j][p]
// ---------------------------------------------------------------------------
__global__ __launch_bounds__(128) void k_h0c0(
    const float* __restrict__ Wh, const float* __restrict__ bh,
    const float* __restrict__ Wc, const float* __restrict__ bc)
{
    extern __shared__ float sm[];
    float* shH  = sm;                  // 13056 floats
    float* shWh = sm + 13056;          // 4224
    float* shWc = shWh + 4224;         // 4224

    const int blk = blockIdx.x;
    const int b = blk >> 5, y = blk & 31;
    const int tid = threadIdx.x;

    {
        const float4* src4 = (const float4*)g_hid;
        float4* sh4 = (float4*)shH;
        for (int i = tid; i < 3 * 34 * 32; i += 128) {
            int r = i / (34 * 32);
            int rem = i - r * (34 * 32);
            int xx = rem >> 5, k4 = rem & 31;
            int yy = y + r - 1;
            float4 v = make_float4(0.f, 0.f, 0.f, 0.f);
            if (yy >= 0 && yy < 32 && xx >= 1 && xx <= 32)
                v = src4[((b * 32 + yy) * 32 + (xx - 1)) * 32 + k4];
            sh4[i] = v;
        }
    }

    const int c = tid;
    float accH[32], accC[32];
#pragma unroll
    for (int x = 0; x < 32; ++x) { accH[x] = 0.0f; accC[x] = 0.0f; }

    for (int tap = 0; tap < 9; ++tap) {
        const int r = tap / 3;
        const int dxp = tap % 3;
#pragma unroll 1
        for (int kc = 0; kc < 4; ++kc) {
            __syncthreads();
            for (int i = tid; i < 4096; i += 128) {
                int k = i >> 7, cc = i & 127;
                int gidx = (tap * 128 + kc * 32 + k) * 128 + cc;
                shWh[cc * 33 + k] = Wh[gidx];
                shWc[cc * 33 + k] = Wc[gidx];
            }
            __syncthreads();
#pragma unroll 2
            for (int k4 = 0; k4 < 8; ++k4) {
                const float* wph = &shWh[c * 33 + k4 * 4];
                const float* wpc = &shWc[c * 33 + k4 * 4];
                float wh0 = wph[0], wh1 = wph[1], wh2 = wph[2], wh3 = wph[3];
                float wc0 = wpc[0], wc1 = wpc[1], wc2 = wpc[2], wc3 = wpc[3];
#pragma unroll
                for (int x = 0; x < 32; ++x) {
                    const float4 v = *(const float4*)&shH[(r * 34 + x + dxp) * 128 + kc * 32 + k4 * 4];
                    accH[x] += v.x * wh0; accH[x] += v.y * wh1;
                    accH[x] += v.z * wh2; accH[x] += v.w * wh3;
                    accC[x] += v.x * wc0; accC[x] += v.y * wc1;
                    accC[x] += v.z * wc2; accC[x] += v.w * wc3;
                }
            }
        }
    }

    float bbh = bh[c], bbc = bc[c];
    int p0 = blk * 32;
#pragma unroll
    for (int x = 0; x < 32; ++x) {
        int p = p0 + x;
        g_c[0][c * NPIX + p] = accC[x] + bbc;
        float hv = accH[x] + bbh;
        __nv_bfloat16 hi = __float2bfloat16(hv);
        __nv_bfloat16 lo = __float2bfloat16(hv - __bfloat162float(hi));
        g_h_hi[0][c * NPIX + p] = hi;
        g_h_lo[0][c * NPIX + p] = lo;
    }
}

// ---------------------------------------------------------------------------
// k_step_mma: fused conv_f + HMMA bf16 hi/lo-split GEMM + LSTM epilogue.
// 128 CTAs x 256 threads; M=128 px (4 rows of one image), N=512, K=128.
// ---------------------------------------------------------------------------
struct TileCtx {
    uint32_t smb;
    uint32_t offA0, offA1;
    uint32_t kB2;
    int mt, lane, mf;
    int pixA, pixB;
    int pxlA, pxlB;          // CTA-local pixel indices
    float bfv;
    const float* sWih;
    const float* sBias;
    const float* sInp;       // [2][128] partials
    const float* cOld;
    float* cNew;
    __nv_bfloat16* hHiNew;
    __nv_bfloat16* hLoNew;
};

__device__ __forceinline__ void do_tile(const TileCtx& T, int ch, int nt, uint32_t Bbase)
{
    const int lane = T.lane;
    float acc[2][4][4];
#pragma unroll
    for (int m = 0; m < 2; ++m)
#pragma unroll
        for (int n = 0; n < 4; ++n)
#pragma unroll
            for (int k = 0; k < 4; ++k) acc[m][n][k] = 0.0f;

    const int nrow0 = nt * 32 + (lane & 7) + (((lane >> 3) & 1) << 3);
    const uint32_t swz0 = (nrow0 & 7) << 4;
    const uint32_t pbase0 = nrow0 * 256;
    const uint32_t pbase1 = (nrow0 + 16) * 256;

#pragma unroll
    for (int pass = 0; pass < 3; ++pass) {
        uint32_t Ab = T.smb + SM_A + ((pass == 1) ? 32768 : 0);
        uint32_t Bb = Bbase + ((pass == 2) ? 32768 : 0);
        uint32_t pa0 = Ab + T.offA0;
        uint32_t pa1 = Ab + T.offA1;
        uint32_t pb0 = Bb + pbase0;
        uint32_t pb1 = Bb + pbase1;
#pragma unroll
        for (int ks = 0; ks < 8; ++ks) {
            uint32_t a0[4], a1[4], r0[4], r1[4];
            LDSM4T(a0, pa0);
            LDSM4T(a1, pa1);
            uint32_t kb2 = (uint32_t)(ks * 32) + T.kB2;
            LDSM4(r0, pb0 + (kb2 ^ swz0));
            LDSM4(r1, pb1 + (kb2 ^ swz0));
            mma_bf16(acc[0][0], a0, r0[0], r0[2]);
            mma_bf16(acc[0][1], a0, r0[1], r0[3]);
            mma_bf16(acc[0][2], a0, r1[0], r1[2]);
            mma_bf16(acc[0][3], a0, r1[1], r1[3]);
            mma_bf16(acc[1][0], a1, r0[0], r0[2]);
            mma_bf16(acc[1][1], a1, r0[1], r0[3]);
            mma_bf16(acc[1][2], a1, r1[0], r1[2]);
            mma_bf16(acc[1][3], a1, r1[1], r1[3]);
            pa0 += 4096; pa1 += 4096;
        }
    }

    const float inpA = T.sInp[T.pxlA] + T.sInp[128 + T.pxlA] + T.bfv;
    const float inpB = T.sInp[T.pxlB] + T.sInp[128 + T.pxlB] + T.bfv;

    // ---- fused LSTM epilogue ----
    const int jbase = ch * 32 + nt * 8 + ((lane & 3) >> 1);
#pragma unroll
    for (int nf = 0; nf < 4; ++nf) {
        float send[4], recv[4];
#pragma unroll
        for (int k = 0; k < 4; ++k)
            send[k] = T.mf ? acc[0][nf][k] : acc[1][nf][k];
#pragma unroll
        for (int k = 0; k < 4; ++k)
            recv[k] = __shfl_xor_sync(0xffffffffu, send[k], 1);

        float i1, f1, g1, o1, i2, f2, g2, o2;
        if (T.mf == 0) {
            i1 = acc[0][nf][0]; f1 = acc[0][nf][1];
            i2 = acc[0][nf][2]; f2 = acc[0][nf][3];
            g1 = recv[0]; o1 = recv[1]; g2 = recv[2]; o2 = recv[3];
        } else {
            g1 = acc[1][nf][0]; o1 = acc[1][nf][1];
            g2 = acc[1][nf][2]; o2 = acc[1][nf][3];
            i1 = recv[0]; f1 = recv[1]; i2 = recv[2]; f2 = recv[3];
        }
        const int j = jbase + nf * 2;
        const float wii = T.sWih[j],        wif = T.sWih[128 + j];
        const float wig = T.sWih[256 + j],  wio = T.sWih[384 + j];
        const float bi  = T.sBias[j],       bff = T.sBias[128 + j];
        const float bg  = T.sBias[256 + j], bo  = T.sBias[384 + j];
        const long jbaseN = (long)j * NPIX;

        {
            float gi = i1 + inpA * wii + bi;
            float gf = f1 + inpA * wif + bff;
            float gg = g1 + inpA * wig + bg;
            float go = o1 + inpA * wio + bo;
            float cn = sigf(gf) * T.cOld[jbaseN + T.pixA] + sigf(gi) * tanhx(gg);
            T.cNew[jbaseN + T.pixA] = cn;
            float hv = sigf(go) * tanhx(cn);
            __nv_bfloat16 hi = __float2bfloat16(hv);
            T.hHiNew[jbaseN + T.pixA] = hi;
            T.hLoNew[jbaseN + T.pixA] = __float2bfloat16(hv - __bfloat162float(hi));
        }
        {
            float gi = i2 + inpB * wii + bi;
            float gf = f2 + inpB * wif + bff;
            float gg = g2 + inpB * wig + bg;
            float go = o2 + inpB * wio + bo;
            float cn = sigf(gf) * T.cOld[jbaseN + T.pixB] + sigf(gi) * tanhx(gg);
            T.cNew[jbaseN + T.pixB] = cn;
            float hv = sigf(go) * tanhx(cn);
            __nv_bfloat16 hi = __float2bfloat16(hv);
            T.hHiNew[jbaseN + T.pixB] = hi;
            T.hLoNew[jbaseN + T.pixB] = __float2bfloat16(hv - __bfloat162float(hi));
        }
    }
}

__global__ __launch_bounds__(256) void k_step_mma(
    const float* __restrict__ Wih, const float* __restrict__ bih,
    const float* __restrict__ bhh, const float* __restrict__ Wf,
    const float* __restrict__ bf, int rb)
{
    extern __shared__ char smc[];
    const int tid = threadIdx.x;
    const int warp = tid >> 5, lane = tid & 31;
    const int blk = blockIdx.x;
    const int P0 = blk * 128;
    const int bimg = blk >> 3, y0 = (blk & 7) * 4;
    const uint32_t smb = s2u(smc);
    const __nv_bfloat16* hHi = g_h_hi[rb];
    const __nv_bfloat16* hLo = g_h_lo[rb];

    // ---- issue async B copy for chunk 0 only (buf1 holds X first) ----
    {
        const char* src = g_wblob;
        for (int i = tid; i < 4096; i += 256)
            CPASYNC16(smb + SM_B + i * 16, src + i * 16);
        CPCOMMIT();
    }

    // ---- stage A^T hi/lo: row=k (256B swizzled), col=px ----
    for (int c = tid; c < 2048; c += 256) {
        int k = c >> 4, pc = c & 15;
        uint4 hv = *(const uint4*)&hHi[k * NPIX + P0 + pc * 8];
        uint4 lv = *(const uint4*)&hLo[k * NPIX + P0 + pc * 8];
        uint32_t off = (uint32_t)(k * 256) + (((uint32_t)(pc * 16)) ^ ((uint32_t)((k & 7) << 4)));
        *(uint4*)(smc + SM_A + off) = hv;
        *(uint4*)(smc + SM_A + 32768 + off) = lv;
    }

    // ---- stage X (conv input, hi only) into buf1 region: [k][6 rows][36] ----
    for (int u = tid; u < 3072; u += 256) {
        int k = u / 24, rem = u % 24;
        int r = rem >> 2, q = rem & 3;
        int yy = y0 + r - 1;
        char* dst = smc + SM_X + k * 432 + r * 72 + 4 + q * 16;
        if (yy >= 0 && yy < 32) {
            uint4 v = *(const uint4*)&hHi[k * NPIX + bimg * 1024 + yy * 32 + q * 8];
            ((uint32_t*)dst)[0] = v.x; ((uint32_t*)dst)[1] = v.y;
            ((uint32_t*)dst)[2] = v.z; ((uint32_t*)dst)[3] = v.w;
        } else {
            ((uint32_t*)dst)[0] = 0; ((uint32_t*)dst)[1] = 0;
            ((uint32_t*)dst)[2] = 0; ((uint32_t*)dst)[3] = 0;
        }
    }
    for (int u = tid; u < 768; u += 256) {
        int k = u / 6, r = u % 6;
        *(uint32_t*)(smc + SM_X + k * 432 + r * 72) = 0;        // slots 0,1
        *(uint32_t*)(smc + SM_X + k * 432 + r * 72 + 68) = 0;   // slots 34,35
    }

    // ---- stage gate constants + Wf ----
    {
        float* sWih = (float*)(smc + OFF_WIH);
        float* sBias = (float*)(smc + OFF_BIAS);
        float* sWf = (float*)(smc + OFF_WF);
        for (int i = tid; i < 512; i += 256) {
            sWih[i] = Wih[i];
            sBias[i] = bih[i] + bhh[i];
        }
        for (int i = tid; i < 1152; i += 256) sWf[i] = Wf[i];
    }
    __syncthreads();

    // ---- conv_f partials: thread = (px 0..127, khalf 0..1) ----
    {
        const int cpx = tid & 127, kh = tid >> 7;
        const int ly = cpx >> 5, cx = cpx & 31;
        const char* Xk = smc + SM_X + ly * 72 + cx * 2;
        const float* sWf = (const float*)(smc + OFF_WF);
        float s = 0.0f;
#pragma unroll 1
        for (int k = kh * 64; k < kh * 64 + 64; ++k) {
            const char* kb = Xk + k * 432;
#pragma unroll
            for (int tap = 0; tap < 9; ++tap) {
                int r = tap / 3, dx = tap % 3;
                __nv_bfloat16 v = *(const __nv_bfloat16*)(kb + r * 72 + (dx + 1) * 2);
                s += __bfloat162float(v) * sWf[tap * 128 + k];
            }
        }
        ((float*)(smc + OFF_INP))[kh * 128 + cpx] = s;
    }
    __syncthreads();   // inp done; X region dead

    // ---- now issue chunk 1 into buf1 ----
    {
        const char* src = g_wblob + 65536;
        for (int i = tid; i < 4096; i += 256)
            CPASYNC16(smb + SM_B + 65536 + i * 16, src + i * 16);
        CPCOMMIT();
    }

    // ---- per-warp / per-lane constants ----
    TileCtx T;
    T.smb = smb;
    T.lane = lane;
    T.mt = warp & 3;
    T.mf = lane & 1;
    {
        int kA = (lane & 7) + ((lane >> 4) << 3);
        int pxg = ((lane >> 3) & 1) << 3;
        int px0 = T.mt * 32 + pxg;
        uint32_t swzA = (kA & 7) << 4;
        T.offA0 = (uint32_t)(kA * 256) + (((uint32_t)(px0 * 2)) ^ swzA);
        T.offA1 = (uint32_t)(kA * 256) + (((uint32_t)((px0 + 16) * 2)) ^ swzA);
        T.kB2 = (uint32_t)((lane >> 4) << 4);
    }
    {
        int r = lane >> 2;
        T.pxlA = T.mt * 32 + T.mf * 16 + r;
        T.pxlB = T.pxlA + 8;
        T.pixA = P0 + T.pxlA;
        T.pixB = P0 + T.pxlB;
    }
    T.bfv = bf[0];
    T.sWih = (const float*)(smc + OFF_WIH);
    T.sBias = (const float*)(smc + OFF_BIAS);
    T.sInp = (const float*)(smc + OFF_INP);
    T.cOld = g_c[rb];
    T.cNew = g_c[rb ^ 1];
    T.hHiNew = g_h_hi[rb ^ 1];
    T.hLoNew = g_h_lo[rb ^ 1];

    const int ntg = warp >> 2;

    CPWAIT(1);         // chunk0 done (chunk1 may be in flight)
    __syncthreads();

    // chunk 0 (buf0)
    do_tile(T, 0, ntg * 2 + 0, smb + SM_B);
    do_tile(T, 0, ntg * 2 + 1, smb + SM_B);
    __syncthreads();
    {
        const char* src = g_wblob + 2 * 65536;
        for (int i = tid; i < 4096; i += 256)
            CPASYNC16(smb + SM_B + i * 16, src + i * 16);
        CPCOMMIT();
    }
    CPWAIT(1);         // chunk1 done
    __syncthreads();

    // chunk 1 (buf1)
    do_tile(T, 1, ntg * 2 + 0, smb + SM_B + 65536);
    do_tile(T, 1, ntg * 2 + 1, smb + SM_B + 65536);
    __syncthreads();
    {
        const char* src = g_wblob + 3 * 65536;
        for (int i = tid; i < 4096; i += 256)
            CPASYNC16(smb + SM_B + 65536 + i * 16, src + i * 16);
        CPCOMMIT();
    }
    CPWAIT(1);         // chunk2 done
    __syncthreads();

    // chunk 2 (buf0)
    do_tile(T, 2, ntg * 2 + 0, smb + SM_B);
    do_tile(T, 2, ntg * 2 + 1, smb + SM_B);
    CPWAIT(0);         // chunk3 done
    __syncthreads();

    // chunk 3 (buf1)
    do_tile(T, 3, ntg * 2 + 0, smb + SM_B + 65536);
    do_tile(T, 3, ntg * 2 + 1, smb + SM_B + 65536);
}

// ---------------------------------------------------------------------------
// k_policy: 1x1 conv + softmax. Reads final h buffer [j][p] bf16 hi/lo.
// ---------------------------------------------------------------------------
__global__ __launch_bounds__(256) void k_policy(
    const float* __restrict__ Wpol, float* __restrict__ out)
{
    __shared__ float shH[128 * 66];
    const int blk = blockIdx.x, tid = threadIdx.x;
    const int p0 = blk * 64;
    const __nv_bfloat16* hHi = g_h_hi[NSTEPS & 1];
    const __nv_bfloat16* hLo = g_h_lo[NSTEPS & 1];

    for (int u = tid; u < 128 * 8; u += 256) {
        int k = u >> 3, q = u & 7;
        uint4 hv = *(const uint4*)&hHi[k * NPIX + p0 + q * 8];
        uint4 lv = *(const uint4*)&hLo[k * NPIX + p0 + q * 8];
        const __nv_bfloat16* he = (const __nv_bfloat16*)&hv;
        const __nv_bfloat16* le = (const __nv_bfloat16*)&lv;
#pragma unroll
        for (int e = 0; e < 8; ++e)
            shH[k * 66 + q * 8 + e] = __bfloat162float(he[e]) + __bfloat162float(le[e]);
    }
    __syncthreads();

    const int px = tid >> 2, q = tid & 3;
    const float4* W4 = (const float4*)Wpol;
    float ax = 0.f, ay = 0.f, az = 0.f, aw = 0.f;
#pragma unroll
    for (int k = q * 32; k < q * 32 + 32; ++k) {
        float hv = shH[k * 66 + px];
        float4 w = W4[k];
        ax += hv * w.x; ay += hv * w.y; az += hv * w.z; aw += hv * w.w;
    }
    ax += __shfl_down_sync(0xffffffffu, ax, 2, 4);
    ay += __shfl_down_sync(0xffffffffu, ay, 2, 4);
    az += __shfl_down_sync(0xffffffffu, az, 2, 4);
    aw += __shfl_down_sync(0xffffffffu, aw, 2, 4);
    ax += __shfl_down_sync(0xffffffffu, ax, 1, 4);
    ay += __shfl_down_sync(0xffffffffu, ay, 1, 4);
    az += __shfl_down_sync(0xffffffffu, az, 1, 4);
    aw += __shfl_down_sync(0xffffffffu, aw, 1, 4);

    if (q == 0) {
        const int p = p0 + px;
        const int b = p >> 10, rem = p & 1023;
        float m = fmaxf(fmaxf(ax, ay), fmaxf(az, aw));
        float e0 = __expf(ax - m), e1 = __expf(ay - m);
        float e2 = __expf(az - m), e3 = __expf(aw - m);
        float inv = __fdividef(1.0f, e0 + e1 + e2 + e3);
        const int base = b * 4096 + rem;
        out[base]            = ax;
        out[base + 1024]     = ay;
        out[base + 2048]     = az;
        out[base + 3072]     = aw;
        float* pr = out + 65536;
        pr[base]            = e0 * inv;
        pr[base + 1024]     = e1 * inv;
        pr[base + 2048]     = e2 * inv;
        pr[base + 3072]     = e3 * inv;
    }
}

// ---------------------------------------------------------------------------
extern "C" void kernel_launch(void* const* d_in, const int* in_sizes, int n_in,
                              void* d_out, int out_size)
{
    (void)in_sizes; (void)n_in; (void)out_size;
    const float* mapd  = (const float*)d_in[0];
    const float* goal  = (const float*)d_in[1];
    const float* W_hid = (const float*)d_in[2];
    const float* b_hid = (const float*)d_in[3];
    const float* W_h0  = (const float*)d_in[4];
    const float* b_h0  = (const float*)d_in[5];
    const float* W_c0  = (const float*)d_in[6];
    const float* b_c0  = (const float*)d_in[7];
    const float* W_f   = (const float*)d_in[8];
    const float* b_f   = (const float*)d_in[9];
    const float* W_ih  = (const float*)d_in[10];
    const float* b_ih  = (const float*)d_in[11];
    const float* W_hh  = (const float*)d_in[12];
    const float* b_hh  = (const float*)d_in[13];
    const float* W_pol = (const float*)d_in[14];
    float* out = (float*)d_out;

    const int smem2 = (13056 + 4224 * 2) * 4;          // 86016 B
    cudaFuncSetAttribute(k_h0c0, cudaFuncAttributeMaxDynamicSharedMemorySize, smem2);
    cudaFuncSetAttribute(k_step_mma, cudaFuncAttributeMaxDynamicSharedMemorySize, SMEM_STEP);

    k_hid<<<512, 128>>>(mapd, goal, W_hid, b_hid);
    k_prep<<<512, 256>>>(W_hh);
    k_h0c0<<<512, 128, smem2>>>(W_h0, b_h0, W_c0, b_c0);
    for (int s = 0; s < NSTEPS; ++s)
        k_step_mma<<<128, 256, SMEM_STEP>>>(W_ih, b_ih, b_hh, W_f, b_f, s & 1);
    k_policy<<<256, 256>>>(W_pol, out);
}